// round 6
// baseline (speedup 1.0000x reference)
#include <cuda_runtime.h>
#include <math.h>

#define MARGIN 0.02f
#define EPS 1e-12f
#define K_INST 4
#define DIM 128
#define NMAX 4096

#define TM 128
#define TN 128
#define KC 16
#define ASTR 256        // duplicated-A k-row stride in floats (128 values x2)
#define BSTR 128        // B k-row stride in floats
#define STAGE_F 6144    // floats per stage: A-dup 4096 + B 2048
#define TTILES 32       // n / TM
#define NBLOCKS 528     // TTILES*(TTILES+1)/2
#define NSTAGES 8       // DIM / KC

__device__ double g_tot;
__device__ double g_neg;
__device__ unsigned long long g_nv;
__device__ unsigned int g_ticket;
__device__ int   g_pa[NMAX];          // per-anchor valid-triplet count
__device__ float g_posp[NMAX * 3];    // pos_dist + MARGIN (plain stores, replay-safe)
__device__ float g_sqn[NMAX];         // squared norms

__device__ __forceinline__ float fsqrt_approx(float x) {
    float r;
    asm("sqrt.approx.f32 %0, %1;" : "=f"(r) : "f"(x));
    return r;
}

#define FFMA2(d, a, b, c) \
    asm("fma.rn.f32x2 %0, %1, %2, %3;" : "=l"(d) : "l"(a), "l"(b), "l"(c))

#define UNPACK2(lo, hi, v) \
    asm("mov.b64 {%0, %1}, %2;" : "=f"(lo), "=f"(hi) : "l"(v))

// ---------------------------------------------------------------------------
__global__ void pos_kernel(const float* __restrict__ X, int n) {
    int gwarp = (blockIdx.x * blockDim.x + threadIdx.x) >> 5;
    int lane  = threadIdx.x & 31;
    if (blockIdx.x == 0 && threadIdx.x == 0) {
        g_tot = 0.0; g_neg = 0.0; g_nv = 0ULL; g_ticket = 0u;
    }
    if (gwarp >= n) return;
    int i = gwarp;
    if (lane == 1) g_pa[i] = 0;

    float4 a = ((const float4*)(X + (size_t)i * DIM))[lane];
    float selfsq = a.x * a.x + a.y * a.y + a.z * a.z + a.w * a.w;

    int cs = i & ~(K_INST - 1);
    float dd[K_INST - 1];
    int idx = 0;
    #pragma unroll
    for (int q = 0; q < K_INST; q++) {
        if (cs + q == i) continue;
        float4 b = ((const float4*)(X + (size_t)(cs + q) * DIM))[lane];
        float dx = a.x - b.x, dy = a.y - b.y, dz = a.z - b.z, dw = a.w - b.w;
        dd[idx++] = dx * dx + dy * dy + dz * dz + dw * dw;
    }

    #pragma unroll
    for (int o = 16; o; o >>= 1) {
        selfsq += __shfl_xor_sync(0xFFFFFFFFu, selfsq, o);
        #pragma unroll
        for (int p = 0; p < K_INST - 1; p++)
            dd[p] += __shfl_xor_sync(0xFFFFFFFFu, dd[p], o);
    }

    if (lane == 0) {
        g_sqn[i] = selfsq;
        #pragma unroll
        for (int p = 0; p < K_INST - 1; p++) {
            float d = fsqrt_approx(fmaxf(dd[p], EPS));
            g_posp[i * 3 + p] = d + MARGIN;
        }
    }
}

// ---------------------------------------------------------------------------
// Upper-triangular 128x128 Gram tiles, 8x8 FFMA2 micro-tiles, double-buffered
// register-prefetch pipeline (1 barrier per stage), fused triplet epilogue.
__global__ __launch_bounds__(256, 2) void main_kernel(const float* __restrict__ X,
                                                      float* __restrict__ out, int n) {
    // Triangular tile decode
    int bid = blockIdx.x;
    float tf = 2.0f * TTILES + 1.0f;
    int rowT = (int)((tf - sqrtf(tf * tf - 8.0f * (float)bid)) * 0.5f);
    while ((rowT + 1) * TTILES - ((rowT + 1) * rowT) / 2 <= bid) rowT++;
    while (rowT * TTILES - (rowT * (rowT - 1)) / 2 > bid) rowT--;
    int colT = rowT + (bid - (rowT * TTILES - (rowT * (rowT - 1)) / 2));

    __shared__ __align__(16) float sm[2 * STAGE_F];   // 48 KB, two stages

    int tid = threadIdx.x;
    int tx = tid & 15;       // n-dim (8 cols each)
    int ty = tid >> 4;       // m-dim (8 rows each)
    int rowBase = rowT * TM;
    int colBase = colT * TN;
    bool offdiag = (colT != rowT);

    // Per-thread load coordinates (2 float4 per matrix per stage)
    int c4  = tid & 3;       // float4 index within 16-k chunk
    int r0  = tid >> 2;      // rows 0..63   (l=0)
    int r1  = r0 + 64;       // rows 64..127 (l=1)

    const float* __restrict__ Arow0 = X + (size_t)(rowBase + r0) * DIM + c4 * 4;
    const float* __restrict__ Arow1 = X + (size_t)(rowBase + r1) * DIM + c4 * 4;
    const float* __restrict__ Brow0 = X + (size_t)(colBase + r0) * DIM + c4 * 4;
    const float* __restrict__ Brow1 = X + (size_t)(colBase + r1) * DIM + c4 * 4;

    float4 va, vb, wa, wb;   // prefetch registers

    unsigned long long acc[8][4];   // [row][colpair] packed (c0,c1)
    #pragma unroll
    for (int a = 0; a < 8; a++)
        #pragma unroll
        for (int b = 0; b < 4; b++) acc[a][b] = 0ULL;

    // ---- stage store helper (macro to keep regs in place) ----
#define ST_STAGE(buf)                                                          \
    do {                                                                       \
        float* sA = sm + (buf) * STAGE_F;                                      \
        float* sB = sA + KC * ASTR;                                            \
        _Pragma("unroll")                                                      \
        for (int q = 0; q < 4; q++) {                                          \
            int kk = c4 * 4 + q;                                               \
            float a0 = (&va.x)[q], a1 = (&vb.x)[q];                            \
            int ua0 = ((r0 >> 1) ^ kk) & 63;                                   \
            int ua1 = ((r1 >> 1) ^ kk) & 63;                                   \
            *(float2*)&sA[kk * ASTR + ua0 * 4 + (r0 & 1) * 2] = make_float2(a0, a0); \
            *(float2*)&sA[kk * ASTR + ua1 * 4 + (r1 & 1) * 2] = make_float2(a1, a1); \
            float b0 = (&wa.x)[q], b1 = (&wb.x)[q];                            \
            int ub0 = ((r0 >> 2) ^ kk) & 31;                                   \
            int ub1 = ((r1 >> 2) ^ kk) & 31;                                   \
            sB[kk * BSTR + ub0 * 4 + (r0 & 3)] = b0;                           \
            sB[kk * BSTR + ub1 * 4 + (r1 & 3)] = b1;                           \
        }                                                                      \
    } while (0)

#define LD_STAGE(s)                                                            \
    do {                                                                       \
        int off = (s) * KC;                                                    \
        va = *(const float4*)(Arow0 + off);                                    \
        vb = *(const float4*)(Arow1 + off);                                    \
        wa = *(const float4*)(Brow0 + off);                                    \
        wb = *(const float4*)(Brow1 + off);                                    \
    } while (0)

    // Prologue: fill buffer 0, issue stage-1 loads
    LD_STAGE(0);
    ST_STAGE(0);
    LD_STAGE(1);
    __syncthreads();

    int p = 0;
    #pragma unroll 1
    for (int st = 0; st < NSTAGES; st++) {
        const float* sA = sm + p * STAGE_F;
        const float* sB = sA + KC * ASTR;

        #pragma unroll
        for (int k = 0; k < KC; k++) {
            unsigned long long ap[8];
            #pragma unroll
            for (int j = 0; j < 4; j++) {
                int u = ((ty * 4 + j) ^ k) & 63;
                ulonglong2 t = *(const ulonglong2*)&sA[k * ASTR + u * 4];
                ap[j * 2 + 0] = t.x;
                ap[j * 2 + 1] = t.y;
            }
            unsigned long long bp[4];
            #pragma unroll
            for (int j = 0; j < 2; j++) {
                int u = ((tx * 2 + j) ^ k) & 31;
                ulonglong2 t = *(const ulonglong2*)&sB[k * BSTR + u * 4];
                bp[j * 2 + 0] = t.x;
                bp[j * 2 + 1] = t.y;
            }
            #pragma unroll
            for (int mi = 0; mi < 8; mi++) {
                FFMA2(acc[mi][0], ap[mi], bp[0], acc[mi][0]);
                FFMA2(acc[mi][1], ap[mi], bp[1], acc[mi][1]);
                FFMA2(acc[mi][2], ap[mi], bp[2], acc[mi][2]);
                FFMA2(acc[mi][3], ap[mi], bp[3], acc[mi][3]);
            }
        }

        if (st < NSTAGES - 1) {
            ST_STAGE(p ^ 1);
            __syncthreads();
            if (st < NSTAGES - 2) LD_STAGE(st + 2);
            p ^= 1;
        }
    }
    __syncthreads();   // mainloop buffers dead; epilogue aliases sm below

    // Aliased epilogue scratch (disjoint offsets, all phases ordered by syncs)
    double* psh     = (double*)sm;            // [0..255]   finalizer
    int*    zsh     = (int*)(sm + 512);       // [512..767] finalizer
    int*    colCnt  = (int*)(sm + 768);       // [768..895]
    float*  redT    = sm + 896;               // 8
    float*  redN    = sm + 904;               // 8
    int*    redC    = (int*)(sm + 912);       // 8
    int*    lastFlag= (int*)(sm + 920);

    if (tid < TN) colCnt[tid] = 0;

    // Unpack accumulators
    float accf[8][8];
    #pragma unroll
    for (int mi = 0; mi < 8; mi++)
        #pragma unroll
        for (int cj = 0; cj < 4; cj++)
            UNPACK2(accf[mi][cj * 2], accf[mi][cj * 2 + 1], acc[mi][cj]);

    // Per-thread metadata direct from global (L2-hot, once per block)
    float sqa[8], sqb[8], pa[24], pb[24];
    {
        const float4* s0 = (const float4*)&g_sqn[rowBase + ty * 8];
        float4 t0 = s0[0], t1 = s0[1];
        #pragma unroll
        for (int q = 0; q < 4; q++) { sqa[q] = (&t0.x)[q]; sqa[4 + q] = (&t1.x)[q]; }
        const float4* s1 = (const float4*)&g_sqn[colBase + tx * 8];
        float4 u0 = s1[0], u1 = s1[1];
        #pragma unroll
        for (int q = 0; q < 4; q++) { sqb[q] = (&u0.x)[q]; sqb[4 + q] = (&u1.x)[q]; }
        const float4* p0 = (const float4*)&g_posp[(rowBase + ty * 8) * 3];
        const float4* p1 = (const float4*)&g_posp[(colBase + tx * 8) * 3];
        #pragma unroll
        for (int j = 0; j < 6; j++) {
            float4 v = p0[j];
            float4 w = p1[j];
            #pragma unroll
            for (int q = 0; q < 4; q++) { pa[j * 4 + q] = (&v.x)[q]; pb[j * 4 + q] = (&w.x)[q]; }
        }
    }
    __syncthreads();   // colCnt zeroed before atomics below

    float tsum = 0.0f, nsum = 0.0f;
    int cr[8], cc[8];
    #pragma unroll
    for (int z = 0; z < 8; z++) { cr[z] = 0; cc[z] = 0; }

    #pragma unroll
    for (int mi = 0; mi < 8; mi++) {
        int i = rowBase + ty * 8 + mi;
        int ci = i >> 2;
        float sqi = sqa[mi];
        float pp0 = pa[mi * 3], pp1 = pa[mi * 3 + 1], pp2 = pa[mi * 3 + 2];
        #pragma unroll
        for (int ni = 0; ni < 8; ni++) {
            int j = colBase + tx * 8 + ni;
            if (!offdiag && (j >> 2) == ci) continue;
            float d2 = sqi + sqb[ni] - 2.0f * accf[mi][ni];
            float d  = fsqrt_approx(fmaxf(d2, EPS));
            float t0 = pp0 - d, t1 = pp1 - d, t2 = pp2 - d;
            if (t0 > 0.0f) { tsum += t0; cr[mi]++; }
            if (t1 > 0.0f) { tsum += t1; cr[mi]++; }
            if (t2 > 0.0f) { tsum += t2; cr[mi]++; }
            if (offdiag) {
                nsum += 2.0f * d;
                float u0 = pb[ni * 3] - d, u1 = pb[ni * 3 + 1] - d, u2 = pb[ni * 3 + 2] - d;
                if (u0 > 0.0f) { tsum += u0; cc[ni]++; }
                if (u1 > 0.0f) { tsum += u1; cc[ni]++; }
                if (u2 > 0.0f) { tsum += u2; cc[ni]++; }
            } else {
                nsum += d;
            }
        }
    }

    int cnt = 0;
    #pragma unroll
    for (int z = 0; z < 8; z++) cnt += cr[z] + cc[z];

    // Row-anchor counts (lane = (ty&1)*16 + tx; xor<=8 reduces over tx)
    #pragma unroll
    for (int mi = 0; mi < 8; mi++) {
        int v = cr[mi];
        v += __shfl_xor_sync(0xFFFFFFFFu, v, 1);
        v += __shfl_xor_sync(0xFFFFFFFFu, v, 2);
        v += __shfl_xor_sync(0xFFFFFFFFu, v, 4);
        v += __shfl_xor_sync(0xFFFFFFFFu, v, 8);
        if (tx == 0) atomicAdd(&g_pa[rowBase + ty * 8 + mi], v);
    }

    if (offdiag) {
        #pragma unroll
        for (int ni = 0; ni < 8; ni++)
            if (cc[ni]) atomicAdd(&colCnt[tx * 8 + ni], cc[ni]);
    }

    #pragma unroll
    for (int o = 16; o; o >>= 1) {
        tsum += __shfl_xor_sync(0xFFFFFFFFu, tsum, o);
        nsum += __shfl_xor_sync(0xFFFFFFFFu, nsum, o);
        cnt  += __shfl_xor_sync(0xFFFFFFFFu, cnt,  o);
    }
    int wid = tid >> 5;
    if ((tid & 31) == 0) { redT[wid] = tsum; redN[wid] = nsum; redC[wid] = cnt; }
    __syncthreads();

    if (offdiag && tid < TN) {
        int v = colCnt[tid];
        if (v) atomicAdd(&g_pa[colBase + tid], v);
    }
    if (tid == 0) {
        float ts = 0.0f, ns = 0.0f; int cs = 0;
        #pragma unroll
        for (int w = 0; w < 8; w++) { ts += redT[w]; ns += redN[w]; cs += redC[w]; }
        atomicAdd(&g_tot, (double)ts);
        atomicAdd(&g_neg, (double)ns);
        atomicAdd(&g_nv, (unsigned long long)cs);
        __threadfence();
        unsigned int t = atomicAdd(&g_ticket, 1u);
        lastFlag[0] = (t == (unsigned int)(gridDim.x - 1)) ? 1 : 0;
    }
    __syncthreads();

    // --- Last block finalizes the 4 outputs ---
    if (lastFlag[0]) {
        __threadfence();
        int z = 0;
        for (int i2 = tid; i2 < n; i2 += 256) z += (g_pa[i2] == 0) ? 1 : 0;
        double ps = 0.0;
        for (int i2 = tid; i2 < n * 3; i2 += 256) ps += (double)(g_posp[i2] - MARGIN);
        zsh[tid] = z;
        psh[tid] = ps;
        __syncthreads();
        for (int s = 128; s; s >>= 1) {
            if (tid < s) { zsh[tid] += zsh[tid + s]; psh[tid] += psh[tid + s]; }
            __syncthreads();
        }
        if (tid == 0) {
            double nv = (double)g_nv;
            out[0] = (g_nv > 0ULL) ? (float)(g_tot / nv) : 0.0f;
            out[1] = (float)zsh[0] / (float)n;
            out[2] = (float)(psh[0] / ((double)n * (double)(K_INST - 1)));
            out[3] = (float)(g_neg / ((double)n * (double)(n - K_INST)));
        }
    }
}

// ---------------------------------------------------------------------------
extern "C" void kernel_launch(void* const* d_in, const int* in_sizes, int n_in,
                              void* d_out, int out_size) {
    const float* X = (const float*)d_in[0];
    int n = in_sizes[1];           // targets element count = n (4096)

    pos_kernel<<<(n * 32 + 255) / 256, 256>>>(X, n);
    main_kernel<<<NBLOCKS, 256>>>(X, (float*)d_out, n);
}

// round 7
// speedup vs baseline: 1.0140x; 1.0140x over previous
#include <cuda_runtime.h>
#include <math.h>

#define MARGIN 0.02f
#define EPS 1e-12f
#define K_INST 4
#define DIM 128
#define NMAX 4096

#define TM 128
#define TN 128
#define KC 16
#define NKP 8           // k-pairs per stage
#define ROWF 256        // floats per (kpair) row: 128 float2
#define STAGE_F 4096    // floats per stage: A 2048 + B 2048 (16 KB)
#define TTILES 32       // n / TM
#define NBLOCKS 528     // TTILES*(TTILES+1)/2
#define NSTAGES 8       // DIM / KC
#define THREADS 512

__device__ double g_tot;
__device__ double g_neg;
__device__ unsigned long long g_nv;
__device__ unsigned int g_ticket;
__device__ int   g_pa[NMAX];          // per-anchor valid-triplet count
__device__ float g_posp[NMAX * 3];    // pos_dist + MARGIN (plain stores, replay-safe)
__device__ float g_sqn[NMAX];         // squared norms

__device__ __forceinline__ float fsqrt_approx(float x) {
    float r;
    asm("sqrt.approx.f32 %0, %1;" : "=f"(r) : "f"(x));
    return r;
}

#define FFMA2(d, a, b, c) \
    asm("fma.rn.f32x2 %0, %1, %2, %3;" : "=l"(d) : "l"(a), "l"(b), "l"(c))

#define UNPACK2(lo, hi, v) \
    asm("mov.b64 {%0, %1}, %2;" : "=f"(lo), "=f"(hi) : "l"(v))

// ---------------------------------------------------------------------------
__global__ void pos_kernel(const float* __restrict__ X, int n) {
    int gwarp = (blockIdx.x * blockDim.x + threadIdx.x) >> 5;
    int lane  = threadIdx.x & 31;
    if (blockIdx.x == 0 && threadIdx.x == 0) {
        g_tot = 0.0; g_neg = 0.0; g_nv = 0ULL; g_ticket = 0u;
    }
    if (gwarp >= n) return;
    int i = gwarp;
    if (lane == 1) g_pa[i] = 0;

    float4 a = ((const float4*)(X + (size_t)i * DIM))[lane];
    float selfsq = a.x * a.x + a.y * a.y + a.z * a.z + a.w * a.w;

    int cs = i & ~(K_INST - 1);
    float dd[K_INST - 1];
    int idx = 0;
    #pragma unroll
    for (int q = 0; q < K_INST; q++) {
        if (cs + q == i) continue;
        float4 b = ((const float4*)(X + (size_t)(cs + q) * DIM))[lane];
        float dx = a.x - b.x, dy = a.y - b.y, dz = a.z - b.z, dw = a.w - b.w;
        dd[idx++] = dx * dx + dy * dy + dz * dz + dw * dw;
    }

    #pragma unroll
    for (int o = 16; o; o >>= 1) {
        selfsq += __shfl_xor_sync(0xFFFFFFFFu, selfsq, o);
        #pragma unroll
        for (int p = 0; p < K_INST - 1; p++)
            dd[p] += __shfl_xor_sync(0xFFFFFFFFu, dd[p], o);
    }

    if (lane == 0) {
        g_sqn[i] = selfsq;
        #pragma unroll
        for (int p = 0; p < K_INST - 1; p++) {
            float d = fsqrt_approx(fmaxf(dd[p], EPS));
            g_posp[i * 3 + p] = d + MARGIN;
        }
    }
}

// ---------------------------------------------------------------------------
// Upper-triangular 128x128 Gram tiles. K-packed FFMA2 (no A duplication):
// acc[m][n] = u64 holding (even-k, odd-k) partial sums. 512 threads, 4x8
// micro-tiles, double-buffered register-prefetch, fused triplet epilogue.
__global__ __launch_bounds__(THREADS, 1) void main_kernel(const float* __restrict__ X,
                                                          float* __restrict__ out, int n) {
    // Triangular tile decode
    int bid = blockIdx.x;
    float tf = 2.0f * TTILES + 1.0f;
    int rowT = (int)((tf - sqrtf(tf * tf - 8.0f * (float)bid)) * 0.5f);
    while ((rowT + 1) * TTILES - ((rowT + 1) * rowT) / 2 <= bid) rowT++;
    while (rowT * TTILES - (rowT * (rowT - 1)) / 2 > bid) rowT--;
    int colT = rowT + (bid - (rowT * TTILES - (rowT * (rowT - 1)) / 2));

    __shared__ __align__(16) float sm[2 * STAGE_F];   // 32 KB, two stages

    int tid = threadIdx.x;
    int tx = tid & 15;       // n-dim: cols tx*8 .. +7
    int ty = tid >> 4;       // m-dim: rows ty*4 .. +3  (0..31)
    int rowBase = rowT * TM;
    int colBase = colT * TN;
    bool offdiag = (colT != rowT);

    // Loader coordinates: one float4 per matrix per thread per stage
    int c4 = tid & 3;        // float4 index in 16-k chunk
    int lr = tid >> 2;       // row 0..127
    const float* __restrict__ Arow = X + (size_t)(rowBase + lr) * DIM + c4 * 4;
    const float* __restrict__ Brow = X + (size_t)(colBase + lr) * DIM + c4 * 4;

    // Store positions (16B units): A: pos=(u&1)*32+(u>>1); B: pos=(u&3)*16+(u>>2)
    int su   = lr >> 1;
    int ssub = lr & 1;
    int posA = (su & 1) * 32 + (su >> 1);
    int posB = (su & 3) * 16 + (su >> 2);
    int kp0  = c4 * 2;
    int kp1  = c4 * 2 + 1;

    float4 va, wa;   // prefetch registers

    unsigned long long acc[4][8];   // k-packed (even,odd) partial sums
    #pragma unroll
    for (int a = 0; a < 4; a++)
        #pragma unroll
        for (int b = 0; b < 8; b++) acc[a][b] = 0ULL;

#define LD_STAGE(s)                                                            \
    do {                                                                       \
        int off = (s) * KC;                                                    \
        va = *(const float4*)(Arow + off);                                     \
        wa = *(const float4*)(Brow + off);                                     \
    } while (0)

#define ST_STAGE(buf)                                                          \
    do {                                                                       \
        float* sA = sm + (buf) * STAGE_F;                                      \
        float* sB = sA + NKP * ROWF;                                           \
        *(float2*)&sA[kp0 * ROWF + (posA ^ kp0) * 4 + ssub * 2] =              \
            make_float2(va.x, va.y);                                           \
        *(float2*)&sA[kp1 * ROWF + (posA ^ kp1) * 4 + ssub * 2] =              \
            make_float2(va.z, va.w);                                           \
        *(float2*)&sB[kp0 * ROWF + (posB ^ kp0) * 4 + ssub * 2] =              \
            make_float2(wa.x, wa.y);                                           \
        *(float2*)&sB[kp1 * ROWF + (posB ^ kp1) * 4 + ssub * 2] =              \
            make_float2(wa.z, wa.w);                                           \
    } while (0)

    LD_STAGE(0);
    ST_STAGE(0);
    LD_STAGE(1);
    __syncthreads();

    int p = 0;
    #pragma unroll 1
    for (int st = 0; st < NSTAGES; st++) {
        const float* sA = sm + p * STAGE_F;
        const float* sB = sA + NKP * ROWF;

        #pragma unroll
        for (int kp = 0; kp < NKP; kp++) {
            // A: units ty*2+j at pos (j*32+ty)^kp -> rows ty*4+2j, ty*4+2j+1
            unsigned long long ap[4];
            #pragma unroll
            for (int j = 0; j < 2; j++) {
                ulonglong2 t = *(const ulonglong2*)
                    &sA[kp * ROWF + ((j * 32 + ty) ^ kp) * 4];
                ap[j * 2 + 0] = t.x;
                ap[j * 2 + 1] = t.y;
            }
            // B: units tx*4+j at pos (j*16+tx)^kp -> cols tx*8+2j, tx*8+2j+1
            unsigned long long bp[8];
            #pragma unroll
            for (int j = 0; j < 4; j++) {
                ulonglong2 t = *(const ulonglong2*)
                    &sB[kp * ROWF + ((j * 16 + tx) ^ kp) * 4];
                bp[j * 2 + 0] = t.x;
                bp[j * 2 + 1] = t.y;
            }
            #pragma unroll
            for (int mi = 0; mi < 4; mi++)
                #pragma unroll
                for (int ni = 0; ni < 8; ni++)
                    FFMA2(acc[mi][ni], ap[mi], bp[ni], acc[mi][ni]);
        }

        if (st < NSTAGES - 1) {
            ST_STAGE(p ^ 1);
            __syncthreads();
            if (st < NSTAGES - 2) LD_STAGE(st + 2);
            p ^= 1;
        }
    }
    __syncthreads();   // mainloop buffers dead; epilogue aliases sm below

    // Aliased epilogue scratch
    double* psh      = (double*)sm;             // 512 doubles
    int*    zsh      = (int*)(sm + 1024);       // 512 ints
    int*    colCnt   = (int*)(sm + 1536);       // 128
    float*  redT     = sm + 1664;               // 16
    float*  redN     = sm + 1680;               // 16
    int*    redC     = (int*)(sm + 1696);       // 16
    int*    lastFlag = (int*)(sm + 1712);

    if (tid < TN) colCnt[tid] = 0;

    // Collapse k-packed accumulators
    float accf[4][8];
    #pragma unroll
    for (int mi = 0; mi < 4; mi++)
        #pragma unroll
        for (int ni = 0; ni < 8; ni++) {
            float lo, hi;
            UNPACK2(lo, hi, acc[mi][ni]);
            accf[mi][ni] = lo + hi;
        }

    // Per-thread metadata direct from global (L2-hot)
    float sqa[4], sqb[8], pa[12], pb[24];
    {
        float4 t0 = *(const float4*)&g_sqn[rowBase + ty * 4];
        #pragma unroll
        for (int q = 0; q < 4; q++) sqa[q] = (&t0.x)[q];
        const float4* s1 = (const float4*)&g_sqn[colBase + tx * 8];
        float4 u0 = s1[0], u1 = s1[1];
        #pragma unroll
        for (int q = 0; q < 4; q++) { sqb[q] = (&u0.x)[q]; sqb[4 + q] = (&u1.x)[q]; }
        const float4* p0 = (const float4*)&g_posp[(rowBase + ty * 4) * 3];
        #pragma unroll
        for (int j = 0; j < 3; j++) {
            float4 v = p0[j];
            #pragma unroll
            for (int q = 0; q < 4; q++) pa[j * 4 + q] = (&v.x)[q];
        }
        const float4* p1 = (const float4*)&g_posp[(colBase + tx * 8) * 3];
        #pragma unroll
        for (int j = 0; j < 6; j++) {
            float4 w = p1[j];
            #pragma unroll
            for (int q = 0; q < 4; q++) pb[j * 4 + q] = (&w.x)[q];
        }
    }
    __syncthreads();   // colCnt zeroed before atomics below

    float tsum = 0.0f, nsum = 0.0f;
    int cr[4] = {0, 0, 0, 0};
    int cc[8] = {0, 0, 0, 0, 0, 0, 0, 0};

    #pragma unroll
    for (int mi = 0; mi < 4; mi++) {
        int i = rowBase + ty * 4 + mi;
        int ci = i >> 2;
        float sqi = sqa[mi];
        float pp0 = pa[mi * 3], pp1 = pa[mi * 3 + 1], pp2 = pa[mi * 3 + 2];
        #pragma unroll
        for (int ni = 0; ni < 8; ni++) {
            int j = colBase + tx * 8 + ni;
            if (!offdiag && (j >> 2) == ci) continue;
            float d2 = sqi + sqb[ni] - 2.0f * accf[mi][ni];
            float d  = fsqrt_approx(fmaxf(d2, EPS));
            float t0 = pp0 - d, t1 = pp1 - d, t2 = pp2 - d;
            if (t0 > 0.0f) { tsum += t0; cr[mi]++; }
            if (t1 > 0.0f) { tsum += t1; cr[mi]++; }
            if (t2 > 0.0f) { tsum += t2; cr[mi]++; }
            if (offdiag) {
                nsum += 2.0f * d;
                float u0 = pb[ni * 3] - d, u1 = pb[ni * 3 + 1] - d, u2 = pb[ni * 3 + 2] - d;
                if (u0 > 0.0f) { tsum += u0; cc[ni]++; }
                if (u1 > 0.0f) { tsum += u1; cc[ni]++; }
                if (u2 > 0.0f) { tsum += u2; cc[ni]++; }
            } else {
                nsum += d;
            }
        }
    }

    int cnt = 0;
    #pragma unroll
    for (int z = 0; z < 4; z++) cnt += cr[z];
    #pragma unroll
    for (int z = 0; z < 8; z++) cnt += cc[z];

    // Row-anchor counts: lane = (ty&1)*16 + tx; xor<=8 reduces over tx
    #pragma unroll
    for (int mi = 0; mi < 4; mi++) {
        int v = cr[mi];
        v += __shfl_xor_sync(0xFFFFFFFFu, v, 1);
        v += __shfl_xor_sync(0xFFFFFFFFu, v, 2);
        v += __shfl_xor_sync(0xFFFFFFFFu, v, 4);
        v += __shfl_xor_sync(0xFFFFFFFFu, v, 8);
        if (tx == 0) atomicAdd(&g_pa[rowBase + ty * 4 + mi], v);
    }

    if (offdiag) {
        #pragma unroll
        for (int ni = 0; ni < 8; ni++)
            if (cc[ni]) atomicAdd(&colCnt[tx * 8 + ni], cc[ni]);
    }

    #pragma unroll
    for (int o = 16; o; o >>= 1) {
        tsum += __shfl_xor_sync(0xFFFFFFFFu, tsum, o);
        nsum += __shfl_xor_sync(0xFFFFFFFFu, nsum, o);
        cnt  += __shfl_xor_sync(0xFFFFFFFFu, cnt,  o);
    }
    int wid = tid >> 5;
    if ((tid & 31) == 0) { redT[wid] = tsum; redN[wid] = nsum; redC[wid] = cnt; }
    __syncthreads();

    if (offdiag && tid < TN) {
        int v = colCnt[tid];
        if (v) atomicAdd(&g_pa[colBase + tid], v);
    }
    if (tid == 0) {
        float ts = 0.0f, ns = 0.0f; int cs = 0;
        #pragma unroll
        for (int w = 0; w < 16; w++) { ts += redT[w]; ns += redN[w]; cs += redC[w]; }
        atomicAdd(&g_tot, (double)ts);
        atomicAdd(&g_neg, (double)ns);
        atomicAdd(&g_nv, (unsigned long long)cs);
        __threadfence();
        unsigned int t = atomicAdd(&g_ticket, 1u);
        lastFlag[0] = (t == (unsigned int)(gridDim.x - 1)) ? 1 : 0;
    }
    __syncthreads();

    // --- Last block finalizes the 4 outputs ---
    if (lastFlag[0]) {
        __threadfence();
        int z = 0;
        for (int i2 = tid; i2 < n; i2 += THREADS) z += (g_pa[i2] == 0) ? 1 : 0;
        double ps = 0.0;
        for (int i2 = tid; i2 < n * 3; i2 += THREADS) ps += (double)(g_posp[i2] - MARGIN);
        zsh[tid] = z;
        psh[tid] = ps;
        __syncthreads();
        for (int s = 256; s; s >>= 1) {
            if (tid < s) { zsh[tid] += zsh[tid + s]; psh[tid] += psh[tid + s]; }
            __syncthreads();
        }
        if (tid == 0) {
            double nv = (double)g_nv;
            out[0] = (g_nv > 0ULL) ? (float)(g_tot / nv) : 0.0f;
            out[1] = (float)zsh[0] / (float)n;
            out[2] = (float)(psh[0] / ((double)n * (double)(K_INST - 1)));
            out[3] = (float)(g_neg / ((double)n * (double)(n - K_INST)));
        }
    }
}

// ---------------------------------------------------------------------------
extern "C" void kernel_launch(void* const* d_in, const int* in_sizes, int n_in,
                              void* d_out, int out_size) {
    const float* X = (const float*)d_in[0];
    int n = in_sizes[1];           // targets element count = n (4096)

    pos_kernel<<<(n * 32 + 255) / 256, 256>>>(X, n);
    main_kernel<<<NBLOCKS, THREADS>>>(X, (float*)d_out, n);
}